// round 13
// baseline (speedup 1.0000x reference)
#include <cuda_runtime.h>
#include <cstdint>

// Problem constants
#define B_  8
#define N_  1024
#define C_  64
#define O_  64
#define KM  4          // K+1
#define BN  (B_*N_)    // 8192

// -------- device scratch --------
__device__ float g_sRi[BN], g_sIi[BN], g_sRj[BN], g_sIj[BN];
__device__ float g_rsum[BN];     // 1 / sum_i exp(mag) per (b,j)
__device__ float g_row[BN*8];    // [bn][0..3]=rowR[m], [4..7]=rowI[m]

// ============================================================
// Kernel 1: attention projections. Block = 256 thr handles 64 rows:
// coalesced f4 load to smem, 4 threads per row (16c each), quad-shuffle.
// ============================================================
__global__ void __launch_bounds__(256) k1_proj(
    const float* __restrict__ Xr, const float* __restrict__ Xi,
    const float* __restrict__ awr, const float* __restrict__ awi,
    const float* __restrict__ abr, const float* __restrict__ abi)
{
    __shared__ float xs[2][64][65];   // ~33.3 KB
    __shared__ float wsh[4][64];      // Wr_i, Wi_i, Wr_j, Wi_j

    int tid = threadIdx.x;
    int rbase = blockIdx.x << 6;      // 64 rows per block, 128 blocks
    const float4* XrG = (const float4*)Xr + (size_t)rbase * 16;
    const float4* XiG = (const float4*)Xi + (size_t)rbase * 16;

#pragma unroll
    for (int r = 0; r < 4; r++) {
        int e = r * 256 + tid;        // 0..1023 f4
        int row = e >> 4, cq = e & 15;
        float4 v = XrG[e];
        float4 u = XiG[e];
        xs[0][row][cq*4+0] = v.x; xs[0][row][cq*4+1] = v.y;
        xs[0][row][cq*4+2] = v.z; xs[0][row][cq*4+3] = v.w;
        xs[1][row][cq*4+0] = u.x; xs[1][row][cq*4+1] = u.y;
        xs[1][row][cq*4+2] = u.z; xs[1][row][cq*4+3] = u.w;
    }
    {
        int g = tid >> 6, c = tid & 63;
        float v = (g == 0) ? awr[c] : (g == 1) ? awi[c]
                : (g == 2) ? awr[64 + c] : awi[64 + c];
        wsh[g][c] = v;                // 0=Wr_i 1=Wi_i 2=Wr_j 3=Wi_j
    }
    __syncthreads();

    int row = tid >> 2, q = tid & 3;
    float sRi = 0.f, sIi = 0.f, sRj = 0.f, sIj = 0.f;
#pragma unroll
    for (int ci = 0; ci < 16; ci++) {
        int c = (q << 4) + ci;
        float a = xs[0][row][c], b = xs[1][row][c];
        float wri = wsh[0][c], wii = wsh[1][c];
        float wrj = wsh[2][c], wij = wsh[3][c];
        sRi += a * wri - b * wii;
        sIi += a * wii + b * wri;
        sRj += a * wrj - b * wij;
        sIj += a * wij + b * wrj;
    }
#pragma unroll
    for (int off = 1; off < 4; off <<= 1) {
        sRi += __shfl_xor_sync(0xffffffffu, sRi, off);
        sIi += __shfl_xor_sync(0xffffffffu, sIi, off);
        sRj += __shfl_xor_sync(0xffffffffu, sRj, off);
        sIj += __shfl_xor_sync(0xffffffffu, sIj, off);
    }
    if (q == 0) {
        int bn = rbase + row;
        g_sRi[bn] = sRi + abr[0];
        g_sIi[bn] = sIi + abi[0];
        g_sRj[bn] = sRj;
        g_sIj[bn] = sIj;
    }
}

// ============================================================
// Kernel 2: softmax denominator per (b,j): sum over i of exp(mag).
// ============================================================
__global__ void __launch_bounds__(128) k2_sumexp(
    const float* __restrict__ par, const float* __restrict__ pai)
{
    int bj = blockIdx.x;          // b*N + j
    int b  = bj >> 10;
    float sRj = g_sRj[bj], sIj = g_sIj[bj];
    float a_r = par[0], a_i = pai[0];
    const float* sRi = g_sRi + (b << 10);
    const float* sIi = g_sIi + (b << 10);
    float acc = 0.f;
#pragma unroll
    for (int t = 0; t < N_ / 128; t++) {
        int i = threadIdx.x + t * 128;
        float sr = sRi[i] + sRj;
        float si = sIi[i] + sIj;
        float pr = sr >= 0.f ? sr : a_r * sr;
        float pi = si >= 0.f ? si : a_i * si;
        float r2 = pr * pr + pi * pi;
        float inv = rsqrtf(fmaxf(r2, 1e-30f));
        float mag = r2 * inv;
        acc += __expf(mag);
    }
    __shared__ float sred[4];
#pragma unroll
    for (int off = 16; off; off >>= 1) acc += __shfl_xor_sync(0xffffffffu, acc, off);
    if ((threadIdx.x & 31) == 0) sred[threadIdx.x >> 5] = acc;
    __syncthreads();
    if (threadIdx.x == 0) {
        float t = sred[0] + sred[1] + sred[2] + sred[3];
        g_rsum[bj] = 1.f / t;
    }
}

// ============================================================
// Kernel 3 (HBM-bound): one block per (b,i) row.
// Streams L_real/L_imag exactly once (268 MB) -> g_row (interleaved).
// ============================================================
__global__ void __launch_bounds__(256) k3_main(
    const float* __restrict__ Lr, const float* __restrict__ Li,
    const float* __restrict__ par, const float* __restrict__ pai)
{
    int bi = blockIdx.x;          // b*N + i
    int b  = bi >> 10;
    int i  = bi & 1023;
    int tid = threadIdx.x;
    int j0 = tid * 4;

    float sRi = g_sRi[bi], sIi = g_sIi[bi];
    float a_r = par[0], a_i = pai[0];

    const int bj0 = (b << 10) + j0;
    float4 sRj4 = *(const float4*)(g_sRj + bj0);
    float4 sIj4 = *(const float4*)(g_sIj + bj0);
    float4 rs4  = *(const float4*)(g_rsum + bj0);
    float sRjv[4] = {sRj4.x, sRj4.y, sRj4.z, sRj4.w};
    float sIjv[4] = {sIj4.x, sIj4.y, sIj4.z, sIj4.w};
    float rsv [4] = {rs4.x,  rs4.y,  rs4.z,  rs4.w };

    float ar[4], ai[4];
#pragma unroll
    for (int k = 0; k < 4; k++) {
        float sr = sRi + sRjv[k];
        float si = sIi + sIjv[k];
        float pr = sr >= 0.f ? sr : a_r * sr;
        float pi = si >= 0.f ? si : a_i * si;
        float r2 = pr * pr + pi * pi;
        float inv = rsqrtf(fmaxf(r2, 1e-30f));
        float mag = r2 * inv;
        float e = __expf(mag);
        float sc = e * inv * rsv[k];
        ar[k] = sc * pr;
        ai[k] = sc * pi;
    }

    float accR[4], accI[4];
#pragma unroll
    for (int m = 0; m < 4; m++) { accR[m] = 0.f; accI[m] = 0.f; }

#pragma unroll
    for (int m = 0; m < 4; m++) {
        size_t base = ((size_t)((b * 4 + m) * N_ + i)) * N_ + j0;
        float4 lr = *(const float4*)(Lr + base);
        float4 li = *(const float4*)(Li + base);
        accR[m] += lr.x * ar[0] - li.x * ai[0];
        accR[m] += lr.y * ar[1] - li.y * ai[1];
        accR[m] += lr.z * ar[2] - li.z * ai[2];
        accR[m] += lr.w * ar[3] - li.w * ai[3];
        accI[m] += lr.x * ai[0] + li.x * ar[0];
        accI[m] += lr.y * ai[1] + li.y * ar[1];
        accI[m] += lr.z * ai[2] + li.z * ar[2];
        accI[m] += lr.w * ai[3] + li.w * ar[3];
    }

    __shared__ float sred[8][8];   // [warp][q]
#pragma unroll
    for (int q = 0; q < 8; q++) {
        float x = (q < 4) ? accR[q] : accI[q - 4];
#pragma unroll
        for (int off = 16; off; off >>= 1) x += __shfl_xor_sync(0xffffffffu, x, off);
        if ((tid & 31) == 0) sred[tid >> 5][q] = x;
    }
    __syncthreads();
    if (tid < 8) {
        float x = 0.f;
#pragma unroll
        for (int w = 0; w < 8; w++) x += sred[w][tid];
        g_row[(bi << 3) + tid] = x;    // [bn][0..3]=R, [4..7]=I
    }
}

// ============================================================
// Kernel 4: final einsums, HIGH-OCCUPANCY retile.
// Block 128 thr = (og 0..3 [one f32x2 o-pair], jl 0..31), JT=2;
// block covers 8 o x 64 j. smem = w slice 16 KB + X dbuf 16 KB = 32 KB.
// __launch_bounds__(128,5): ~102 regs -> 5 blocks = 20 warps/SM.
// Grid = 8 oq x 128 jg = 1024.
// ============================================================
#define XSW(j, q) (((j) << 2) | ((q) ^ ((j) & 3) ^ (((j) >> 2) & 3)))

#define FFMA2(acc, a, b) \
    asm("fma.rn.f32x2 %0, %1, %2, %0;" : "+l"(acc) : "l"(a), "l"(b))

#define PACK2(d, s) \
    asm("mov.b64 %0, {%1, %1};" : "=l"(d) : "f"(s))

#define LDS_B64(d, addr) \
    asm("ld.shared.b64 %0, [%1];" : "=l"(d) : "r"(addr))

__global__ void __launch_bounds__(128, 5) k4_out(
    const float* __restrict__ Xr, const float* __restrict__ Xi,
    const float4* __restrict__ wr4, const float4* __restrict__ wi4,
    float* __restrict__ out)
{
    __shared__ float4 ws[1024];          // [mc*4 + {0,1}=wr, {2,3}=wi] : 16 KB
    __shared__ float4 x_s[2][2][256];    // [buf][ri][XSW(j,q)] : 16 KB

    const int tid = threadIdx.x;
    const int og  = tid & 3;             // o-pair selector (2 o)
    const int jl  = tid >> 2;            // 0..31
    const int bx  = blockIdx.x;
    const int jg  = bx & 127;
    const int oq  = bx >> 7;             // 0..7 (8-o slice)
    const int jbase = jg * 64;

    const float4* XrG = (const float4*)Xr + (size_t)jbase * 16;
    const float4* XiG = (const float4*)Xi + (size_t)jbase * 16;

    // ---- w slice load: 256 (m,c) rows x 8 o (2 f4) per tensor ----
#pragma unroll
    for (int r = 0; r < 4; r++) {
        int e    = r * 128 + tid;        // 0..511
        int mc   = e >> 1, half = e & 1;
        ws[mc * 4 + half]     = wr4[mc * 16 + oq * 2 + half];
        ws[mc * 4 + 2 + half] = wi4[mc * 16 + oq * 2 + half];
    }
    // ---- X phase 0 load ----
#pragma unroll
    for (int r = 0; r < 2; r++) {
        int e = r * 128 + tid;           // 0..255
        int j = e >> 2, q = e & 3;
        int si = XSW(j, q);
        x_s[0][0][si] = XrG[j * 16 + q];
        x_s[0][1][si] = XiG[j * 16 + q];
    }
    __syncthreads();

    // f32x2 accumulators: one o-pair per (m, jt, ri) -> 16 u64 = 32 regs
    uint64_t PR0[4], PI0[4], PR1[4], PI1[4];
#pragma unroll
    for (int m = 0; m < 4; m++) {
        PR0[m] = 0ull; PI0[m] = 0ull;
        PR1[m] = 0ull; PI1[m] = 0ull;
    }

    const uint32_t wb = (uint32_t)__cvta_generic_to_shared(ws) + og * 8;
    const int j0 = jl, j1 = jl + 32;

#pragma unroll
    for (int p = 0; p < 4; p++) {
        int buf = p & 1;
        if (p < 3) {
            int nb = buf ^ 1;
#pragma unroll
            for (int r = 0; r < 2; r++) {
                int e = r * 128 + tid;
                int j = e >> 2, q = e & 3;
                int si = XSW(j, q);
                x_s[nb][0][si] = XrG[j * 16 + (p + 1) * 4 + q];
                x_s[nb][1][si] = XiG[j * 16 + (p + 1) * 4 + q];
            }
        }
#pragma unroll
        for (int q = 0; q < 4; q++) {
            float4 xr0 = x_s[buf][0][XSW(j0, q)];
            float4 xi0 = x_s[buf][1][XSW(j0, q)];
            float4 xr1 = x_s[buf][0][XSW(j1, q)];
            float4 xi1 = x_s[buf][1][XSW(j1, q)];
            const float* fxr0 = (const float*)&xr0;
            const float* fxi0 = (const float*)&xi0;
            const float* fxr1 = (const float*)&xr1;
            const float* fxi1 = (const float*)&xi1;
#pragma unroll
            for (int ci = 0; ci < 4; ci++) {
                const int c = p * 16 + q * 4 + ci;
                uint64_t a0p, b0p, a1p, b1p;
                PACK2(a0p, fxr0[ci]);
                PACK2(b0p, fxi0[ci]);
                PACK2(a1p, fxr1[ci]);
                PACK2(b1p, fxi1[ci]);
#pragma unroll
                for (int m = 0; m < 4; m++) {
                    const uint32_t off = (uint32_t)(((m << 6) + c) << 6);  // mc*64 B
                    uint64_t w0, v0;
                    LDS_B64(w0, wb + off);          // wr o-pair
                    LDS_B64(v0, wb + off + 32);     // wi o-pair
                    FFMA2(PR0[m], a0p, w0);
                    FFMA2(PI0[m], b0p, v0);
                    FFMA2(PR1[m], a1p, w0);
                    FFMA2(PI1[m], b1p, v0);
                }
            }
        }
        __syncthreads();
    }

    // ---- combine over m with row vectors and store (float2 per jt) ----
#pragma unroll
    for (int jt = 0; jt < 2; jt++) {
        int jj = jbase + jl + jt * 32;       // global bn
        const float4* row4 = (const float4*)g_row;
        float4 rR = row4[jj * 2];
        float4 rI = row4[jj * 2 + 1];
        const float* aR = (const float*)&rR;
        const float* aI = (const float*)&rI;

        float2 re = make_float2(0.f, 0.f);
        float2 im = make_float2(0.f, 0.f);
#pragma unroll
        for (int m = 0; m < 4; m++) {
            float a  = aR[m];
            float bi = aI[m];
            float2 pr = jt ? *(float2*)&PR1[m] : *(float2*)&PR0[m];
            float2 pi = jt ? *(float2*)&PI1[m] : *(float2*)&PI0[m];
            re.x += a * pr.x - bi * pi.x;  re.y += a * pr.y - bi * pi.y;
            im.x += bi * pr.x + a * pi.x;  im.y += bi * pr.y + a * pi.y;
        }
        ((float2*)out)[(size_t)jj * 32 + oq * 4 + og] = re;                      // real
        ((float2*)out)[(size_t)BN * 32 + (size_t)jj * 32 + oq * 4 + og] = im;    // imag
    }
}

// ============================================================
extern "C" void kernel_launch(void* const* d_in, const int* in_sizes, int n_in,
                              void* d_out, int out_size)
{
    const float* Xr  = (const float*)d_in[0];
    const float* Xi  = (const float*)d_in[1];
    const float* Lr  = (const float*)d_in[2];
    const float* Li  = (const float*)d_in[3];
    const float* wr  = (const float*)d_in[4];
    const float* wi  = (const float*)d_in[5];
    const float* awr = (const float*)d_in[6];
    const float* awi = (const float*)d_in[7];
    const float* abr = (const float*)d_in[8];
    const float* abi = (const float*)d_in[9];
    const float* par = (const float*)d_in[10];
    const float* pai = (const float*)d_in[11];
    float* out = (float*)d_out;

    k1_proj  <<<BN / 64, 256>>>(Xr, Xi, awr, awi, abr, abi);
    k2_sumexp<<<BN,      128>>>(par, pai);
    k3_main  <<<BN,      256>>>(Lr, Li, par, pai);
    k4_out   <<<8 * 128, 128>>>(Xr, Xi, (const float4*)wr, (const float4*)wi, out);
}